// round 10
// baseline (speedup 1.0000x reference)
#include <cuda_runtime.h>
#include <cuda_bf16.h>
#include <cstdint>

// Problem constants
#define BB 8
#define NN 2048
#define DD 256
#define LL 2
#define MROWS (BB * NN)   // 16384

#define KC 64
#define NSTAGES 3

// smem geometry (padded, no swizzle)
#define PADK 72
#define ROWB (PADK * 2)              // 144 B per row
#define ASTAGE (128 * ROWB)          // 18432 B
#define STAGE_BYTES (2 * ASTAGE)     // 36864 B
#define MMA_SMEM (NSTAGES * STAGE_BYTES)  // 110592 B

// ---------------------------------------------------------------------------
// Scratch
// ---------------------------------------------------------------------------
__device__ __nv_bfloat16 g_adj_bf[(size_t)BB * NN * NN];
__device__ __nv_bfloat16 g_nodes_bf[(size_t)MROWS * DD];
__device__ __nv_bfloat16 g_xbf[(size_t)MROWS * DD];
__device__ __nv_bfloat16 g_xT[(size_t)BB * DD * NN];    // nodes^T (layer-0 B)
__device__ __nv_bfloat16 g_xT2[(size_t)BB * DD * NN];   // x1^T (layer-1 B)
__device__ __nv_bfloat16 g_S[(size_t)MROWS * DD];
__device__ __nv_bfloat16 g_W0bf[(size_t)LL * DD * DD];
__device__ __nv_bfloat16 g_Wrbf[(size_t)LL * DD * DD];
__device__ float g_denom[MROWS];
__device__ int g_ctr[272];   // [0,128): c1 pair, [128,136): c2 batch, [144,272): c3 pair

// ---------------------------------------------------------------------------
// PTX helpers
// ---------------------------------------------------------------------------
__device__ __forceinline__ uint32_t smem_u32(const void* p) {
    uint32_t a;
    asm("{ .reg .u64 t; cvta.to.shared.u64 t, %1; cvt.u32.u64 %0, t; }" : "=r"(a) : "l"(p));
    return a;
}
__device__ __forceinline__ void cp_async16(uint32_t saddr, const void* g) {
    asm volatile("cp.async.cg.shared.global [%0], [%1], 16;" :: "r"(saddr), "l"(g) : "memory");
}
__device__ __forceinline__ void cp_commit() {
    asm volatile("cp.async.commit_group;" ::: "memory");
}
template <int N>
__device__ __forceinline__ void cp_wait() {
    asm volatile("cp.async.wait_group %0;" :: "n"(N) : "memory");
}
__device__ __forceinline__ void ldsm_x4(uint32_t (&r)[4], uint32_t addr) {
    asm volatile("ldmatrix.sync.aligned.m8n8.x4.shared.b16 {%0,%1,%2,%3}, [%4];"
                 : "=r"(r[0]), "=r"(r[1]), "=r"(r[2]), "=r"(r[3]) : "r"(addr));
}
__device__ __forceinline__ void mma_bf16(float (&c)[4], const uint32_t (&a)[4],
                                         uint32_t b0, uint32_t b1) {
    asm volatile(
        "mma.sync.aligned.m16n8k16.row.col.f32.bf16.bf16.f32 "
        "{%0,%1,%2,%3}, {%4,%5,%6,%7}, {%8,%9}, {%0,%1,%2,%3};"
        : "+f"(c[0]), "+f"(c[1]), "+f"(c[2]), "+f"(c[3])
        : "r"(a[0]), "r"(a[1]), "r"(a[2]), "r"(a[3]), "r"(b0), "r"(b1));
}
__device__ __forceinline__ uint32_t pack_bf16x2(float x, float y) {
    __nv_bfloat162 v = __floats2bfloat162_rn(x, y);
    return *(uint32_t*)&v;
}
__device__ __forceinline__ void cvt8(__nv_bfloat16* t, float4 v0, float4 v1) {
    t[0] = __float2bfloat16(v0.x); t[1] = __float2bfloat16(v0.y);
    t[2] = __float2bfloat16(v0.z); t[3] = __float2bfloat16(v0.w);
    t[4] = __float2bfloat16(v1.x); t[5] = __float2bfloat16(v1.y);
    t[6] = __float2bfloat16(v1.z); t[7] = __float2bfloat16(v1.w);
}
// inter-CTA sync (all payload moves via cp.async.cg -> L2-coherent)
__device__ __forceinline__ void ctr_signal(int* c) {
    __syncthreads();
    __threadfence();
    if (threadIdx.x == 0) atomicAdd(c, 1);
}
__device__ __forceinline__ void ctr_wait(int* c, int target) {
    if (threadIdx.x == 0) {
        while (atomicAdd(c, 0) < target) { }
        __threadfence();
    }
    __syncthreads();
}

// ---------------------------------------------------------------------------
// Prologue: adj->bf16 + denom; nodes fp32 -> bf16 plain + transposed; weights
//   blocks [0, MROWS): adj rows (block 0 also zeroes counters)
//   blocks [MROWS, +256): nodes transpose tiles
//   blocks [.., +2*NB_W): weights
// ---------------------------------------------------------------------------
#define NB_W ((LL * DD * DD) / (256 * 8))   // 64

__global__ void prologue_kernel(const float* __restrict__ adj,
                                const float* __restrict__ nodes,
                                const float* __restrict__ W0w,
                                const float* __restrict__ Wrw) {
    int bid = blockIdx.x;
    int tid = threadIdx.x;

    if (bid < MROWS) {
        if (bid == 0) {
            for (int k = tid; k < 272; k += 256) g_ctr[k] = 0;
        }
        int row = bid;
        const float4* src = (const float4*)(adj + (size_t)row * NN);
        __nv_bfloat16* dst = g_adj_bf + (size_t)row * NN;
        float4 v0 = src[tid * 2 + 0];
        float4 v1 = src[tid * 2 + 1];
        float s = v0.x + v0.y + v0.z + v0.w + v1.x + v1.y + v1.z + v1.w;
        __nv_bfloat16 tmp[8];
        cvt8(tmp, v0, v1);
        *(uint4*)(dst + tid * 8) = *(const uint4*)tmp;

        __shared__ float red[8];
#pragma unroll
        for (int o = 16; o; o >>= 1) s += __shfl_xor_sync(0xffffffffu, s, o);
        if ((tid & 31) == 0) red[tid >> 5] = s;
        __syncthreads();
        if (tid < 8) {
            float t = red[tid];
#pragma unroll
            for (int o = 4; o; o >>= 1) t += __shfl_xor_sync(0xffu, t, o);
            if (tid == 0) g_denom[row] = t + 1.0f;
        }
        return;
    }

    int t = bid - MROWS;
    if (t < 256) {
        // nodes: fp32 -> bf16, write plain + transposed (128x128 tile)
        __shared__ __nv_bfloat16 sm[128 * 144];
        int dt = t & 1, nt = (t >> 1) & 15, bb = t >> 5;
#pragma unroll
        for (int it = 0; it < 8; ++it) {
            int idx = it * 256 + tid;
            int rr = idx >> 4, ch = idx & 15;
            size_t off = ((size_t)bb * NN + nt * 128 + rr) * DD + dt * 128 + ch * 8;
            float4 v0 = *(const float4*)(nodes + off);
            float4 v1 = *(const float4*)(nodes + off + 4);
            __nv_bfloat16 tmp[8];
            cvt8(tmp, v0, v1);
            uint4 pk = *(const uint4*)tmp;
            *(uint4*)&sm[rr * 144 + ch * 8] = pk;
            *(uint4*)(g_nodes_bf + off) = pk;
        }
        __syncthreads();
#pragma unroll
        for (int it = 0; it < 8; ++it) {
            int idx = it * 256 + tid;
            int d = idx >> 4, ch = idx & 15;
            __nv_bfloat16 tmp[8];
#pragma unroll
            for (int j = 0; j < 8; ++j) tmp[j] = sm[(ch * 8 + j) * 144 + d];
            *(uint4*)(g_xT + (size_t)bb * DD * NN + (size_t)(dt * 128 + d) * NN
                      + nt * 128 + ch * 8) = *(const uint4*)tmp;
        }
        return;
    }

    int b2 = t - 256;
    const float* src;
    __nv_bfloat16* dst;
    size_t off;
    if (b2 < NB_W) { src = W0w; dst = g_W0bf; off = (size_t)b2 * 256 * 8; }
    else           { src = Wrw; dst = g_Wrbf; off = (size_t)(b2 - NB_W) * 256 * 8; }
    size_t p = off + (size_t)tid * 8;
    float4 v0 = *(const float4*)(src + p);
    float4 v1 = *(const float4*)(src + p + 4);
    __nv_bfloat16 tmp[8];
    cvt8(tmp, v0, v1);
    *(uint4*)(dst + p) = *(const uint4*)tmp;
}

// ---------------------------------------------------------------------------
// Fused persistent GCN kernel: 256 CTAs (all resident at 2/SM), 4 phases
//   CTA (b, r, c):  nn(l0) -> pair-sync -> epi(l0) -> batch-sync ->
//                   nn(l1) -> pair-sync -> epi(l1, final)
// ---------------------------------------------------------------------------
__global__ void __launch_bounds__(256, 2)
fused_gcn_kernel(const float* __restrict__ nodes,
                 const float* __restrict__ W0b,
                 const float* __restrict__ Wrb,
                 float* __restrict__ dout) {
    extern __shared__ char smem[];
    uint32_t sb = smem_u32(smem);
    __nv_bfloat16* Ts = (__nv_bfloat16*)smem;   // aliases stages (epi-l0 epilogue)

    int tid = threadIdx.x;
    int lane = tid & 31, wid = tid >> 5;
    int warp_m = wid & 3, warp_n = wid >> 2;
    int i = blockIdx.x;
    int c = i & 1, r = (i >> 1) & 15, b = i >> 5;
    int row0 = r * 128;              // in-batch
    int col0 = c * 128;
    size_t growbase = (size_t)b * NN + row0;
    int g = lane >> 2, tg = lane & 3;

    uint32_t a_base = sb + (uint32_t)((warp_m * 32 + (lane & 15)) * ROWB + (lane >> 4) * 16);
    uint32_t b_base = sb + ASTAGE +
                      (uint32_t)((warp_n * 64 + (lane & 15)) * ROWB + (lane >> 4) * 16);

    float acc[2][8][4];

    auto zero_acc = [&] {
#pragma unroll
        for (int x = 0; x < 2; ++x)
#pragma unroll
            for (int j = 0; j < 8; ++j)
#pragma unroll
                for (int q = 0; q < 4; ++q) acc[x][j][q] = 0.f;
    };

    auto compute_stage = [&](int s) {
        uint32_t as = a_base + s * STAGE_BYTES;
        uint32_t bs = b_base + s * STAGE_BYTES;
#pragma unroll
        for (int ks = 0; ks < 4; ++ks) {
            uint32_t af[2][4];
            ldsm_x4(af[0], as + 0 * 16 * ROWB + ks * 32);
            ldsm_x4(af[1], as + 1 * 16 * ROWB + ks * 32);
            uint32_t bf[4][4];
#pragma unroll
            for (int n2 = 0; n2 < 4; ++n2)
                ldsm_x4(bf[n2], bs + n2 * 16 * ROWB + ks * 32);
#pragma unroll
            for (int mf = 0; mf < 2; ++mf)
#pragma unroll
                for (int nf = 0; nf < 8; ++nf)
                    mma_bf16(acc[mf][nf], af[mf], bf[nf >> 1][nf & 1],
                             bf[nf >> 1][(nf & 1) + 2]);
        }
    };

    // loaders: nn operands have row stride NN; epi operands stride DD
    auto load_nn = [&](const __nv_bfloat16* Ag, const __nv_bfloat16* Bg,
                       int cc, int s) {
        uint32_t as = sb + s * STAGE_BYTES;
        uint32_t bs = as + ASTAGE;
        int k0 = cc * KC;
#pragma unroll
        for (int it = 0; it < 4; ++it) {
            int idx = it * 256 + tid;
            int rr = idx >> 3, ch = idx & 7;
            cp_async16(as + rr * ROWB + ch * 16, Ag + (size_t)rr * NN + k0 + ch * 8);
        }
#pragma unroll
        for (int it = 0; it < 4; ++it) {
            int idx = it * 256 + tid;
            int rr = idx >> 3, ch = idx & 7;
            cp_async16(bs + rr * ROWB + ch * 16, Bg + (size_t)rr * NN + k0 + ch * 8);
        }
        cp_commit();
    };
    auto load_epi = [&](const __nv_bfloat16* Ag, const __nv_bfloat16* Bg,
                        int k0, int s) {
        uint32_t as = sb + s * STAGE_BYTES;
        uint32_t bs = as + ASTAGE;
#pragma unroll
        for (int it = 0; it < 4; ++it) {
            int idx = it * 256 + tid;
            int rr = idx >> 3, ch = idx & 7;
            cp_async16(as + rr * ROWB + ch * 16, Ag + (size_t)rr * DD + k0 + ch * 8);
        }
#pragma unroll
        for (int it = 0; it < 4; ++it) {
            int idx = it * 256 + tid;
            int rr = idx >> 3, ch = idx & 7;
            cp_async16(bs + rr * ROWB + ch * 16, Bg + (size_t)rr * DD + k0 + ch * 8);
        }
        cp_commit();
    };

    for (int l = 0; l < 2; ++l) {
        // ---------- nn: S tile = adj[b, row0.., :] @ xT[b, col0.., :]^T ----------
        const __nv_bfloat16* Ag = g_adj_bf + (size_t)b * NN * NN + (size_t)row0 * NN;
        const __nv_bfloat16* Bg = (l ? g_xT2 : g_xT) + (size_t)b * DD * NN
                                  + (size_t)col0 * NN;
        zero_acc();
        load_nn(Ag, Bg, 0, 0);
        load_nn(Ag, Bg, 1, 1);
        for (int cc = 0; cc < 32; ++cc) {
            if (cc + 1 < 32) cp_wait<1>(); else cp_wait<0>();
            __syncthreads();
            if (cc + 2 < 32) load_nn(Ag, Bg, cc + 2, (cc + 2) % NSTAGES);
            compute_stage(cc % NSTAGES);
        }
#pragma unroll
        for (int mf = 0; mf < 2; ++mf)
#pragma unroll
            for (int half = 0; half < 2; ++half) {
                int rl = warp_m * 32 + mf * 16 + half * 8 + g;
#pragma unroll
                for (int nf = 0; nf < 8; ++nf) {
                    int col = col0 + warp_n * 64 + nf * 8 + tg * 2;
                    *(uint32_t*)(g_S + (growbase + rl) * DD + col) =
                        pack_bf16x2(acc[mf][nf][half * 2 + 0], acc[mf][nf][half * 2 + 1]);
                }
            }
        int* cnn = (l ? g_ctr + 144 : g_ctr) + b * 16 + r;
        ctr_signal(cnn);
        ctr_wait(cnn, 2);    // both col tiles of this (b, r) done

        // ---------- epi: acc = S@Wr^T + x@W0^T, fused epilogue ----------
        const __nv_bfloat16* A0 = g_S + growbase * DD;
        const __nv_bfloat16* A1 = (l ? g_xbf : g_nodes_bf) + growbase * DD;
        const __nv_bfloat16* B0 = g_Wrbf + (size_t)l * DD * DD + (size_t)col0 * DD;
        const __nv_bfloat16* B1 = g_W0bf + (size_t)l * DD * DD + (size_t)col0 * DD;
        const float* b0p = W0b + l * DD;
        const float* brp = Wrb + l * DD;

        zero_acc();
        load_epi(A0, B0, 0, 0);
        load_epi(A0, B0, KC, 1);
        for (int cc = 0; cc < 8; ++cc) {
            if (cc + 1 < 8) cp_wait<1>(); else cp_wait<0>();
            __syncthreads();
            if (cc + 2 < 8) {
                int nc = cc + 2;
                load_epi(nc < 4 ? A0 : A1, nc < 4 ? B0 : B1, (nc & 3) * KC,
                         nc % NSTAGES);
            }
            compute_stage(cc % NSTAGES);
        }

        if (l == 1) {
            // final: dout = nodes + relu((acc + b0 + (den-1)*br)/den)
#pragma unroll
            for (int mf = 0; mf < 2; ++mf)
#pragma unroll
                for (int half = 0; half < 2; ++half) {
                    int rl = warp_m * 32 + mf * 16 + half * 8 + g;
                    size_t grow = growbase + rl;
                    float den = g_denom[grow];
                    float inv = 1.0f / den;
                    float rs = den - 1.0f;
#pragma unroll
                    for (int nf = 0; nf < 8; ++nf) {
                        int m = col0 + warp_n * 64 + nf * 8 + tg * 2;
                        float2 bi0 = *(const float2*)(b0p + m);
                        float2 bir = *(const float2*)(brp + m);
                        float vx = fmaxf((acc[mf][nf][half * 2 + 0] + bi0.x + rs * bir.x) * inv, 0.f);
                        float vy = fmaxf((acc[mf][nf][half * 2 + 1] + bi0.y + rs * bir.y) * inv, 0.f);
                        float2 nd = *(const float2*)(nodes + grow * DD + m);
                        *(float2*)(dout + grow * DD + m) = make_float2(vx + nd.x, vy + nd.y);
                    }
                }
        } else {
            // x1 = relu(...); write plain g_xbf + transposed g_xT2 (via Ts)
            __syncthreads();   // stage smem fully consumed; alias as Ts
#pragma unroll
            for (int mf = 0; mf < 2; ++mf)
#pragma unroll
                for (int half = 0; half < 2; ++half) {
                    int rl = warp_m * 32 + mf * 16 + half * 8 + g;
                    size_t grow = growbase + rl;
                    float den = g_denom[grow];
                    float inv = 1.0f / den;
                    float rs = den - 1.0f;
#pragma unroll
                    for (int nf = 0; nf < 8; ++nf) {
                        int cl = warp_n * 64 + nf * 8 + tg * 2;
                        int m = col0 + cl;
                        float2 bi0 = *(const float2*)(b0p + m);
                        float2 bir = *(const float2*)(brp + m);
                        float vx = fmaxf((acc[mf][nf][half * 2 + 0] + bi0.x + rs * bir.x) * inv, 0.f);
                        float vy = fmaxf((acc[mf][nf][half * 2 + 1] + bi0.y + rs * bir.y) * inv, 0.f);
                        *(uint32_t*)(g_xbf + grow * DD + m) = pack_bf16x2(vx, vy);
                        Ts[(size_t)cl * 136 + rl] = __float2bfloat16(vx);
                        Ts[(size_t)(cl + 1) * 136 + rl] = __float2bfloat16(vy);
                    }
                }
            __syncthreads();
            int dl = tid >> 1, seg = tid & 1;
            __nv_bfloat16* dst = g_xT2 + (size_t)b * DD * NN
                                 + (size_t)(col0 + dl) * NN + row0 + seg * 64;
            const __nv_bfloat16* srcp = Ts + (size_t)dl * 136 + seg * 64;
#pragma unroll
            for (int q = 0; q < 8; ++q)
                *(uint4*)(dst + q * 8) = *(const uint4*)(srcp + q * 8);

            ctr_signal(g_ctr + 128 + b);
            ctr_wait(g_ctr + 128 + b, 32);   // all batch-b epi(l0) done
        }
    }
}

// ---------------------------------------------------------------------------
// Launch: exactly two kernels
// ---------------------------------------------------------------------------
extern "C" void kernel_launch(void* const* d_in, const int* in_sizes, int n_in,
                              void* d_out, int out_size) {
    const float* nodes = (const float*)d_in[0];
    const float* adj   = (const float*)d_in[1];
    const float* W0w   = (const float*)d_in[2];
    const float* W0b   = (const float*)d_in[3];
    const float* Wrw   = (const float*)d_in[4];
    const float* Wrb   = (const float*)d_in[5];
    float* out = (float*)d_out;

    cudaFuncSetAttribute(fused_gcn_kernel,
                         cudaFuncAttributeMaxDynamicSharedMemorySize, MMA_SMEM);

    prologue_kernel<<<MROWS + 256 + 2 * NB_W, 256>>>(adj, nodes, W0w, Wrw);
    fused_gcn_kernel<<<256, 256, MMA_SMEM>>>(nodes, W0b, Wrb, out);
}